// round 3
// baseline (speedup 1.0000x reference)
#include <cuda_runtime.h>
#include <cstdint>

#define S_LEN 2048
#define BATCH 256
#define INSZ  32
#define HID   8
#define G4    32          // 4*HID gates
#define NBLK  80
#define OUTSZ 128
#define NROWS (S_LEN*BATCH)   // 524288

// Scratch (__device__ globals; no runtime allocation)
__device__ float g_xg[(size_t)NROWS * G4];   // 64 MB: x@W_ih^T + bias, pre-scaled
__device__ float g_ys[(size_t)NROWS * HID];  // 16 MB: LSTM hidden outputs
__device__ float g_dump[BATCH * 32];         // write sink for k2 lanes 8-31

__device__ __forceinline__ float tanha(float x) {
    float r; asm("tanh.approx.f32 %0, %1;" : "=f"(r) : "f"(x)); return r;
}
__device__ __forceinline__ float leaky(float v) { return fmaxf(v, 0.01f * v); }

// ---------------------------------------------------------------------------
// K1: xg[row][g] = s(g) * ( x[row].w_ih[g] + b_ih[g] + b_hh[g] )
//     s = 0.5 for sigmoid gates (i,f,o), 1.0 for tanh gate (g).
//     Coalesced staging of x into smem; lane = gate, rows sequential:
//     broadcast LDS.128 for x, weights in registers, coalesced STG.32.
// ---------------------------------------------------------------------------
__global__ void __launch_bounds__(256) k1_xw(
    const float* __restrict__ x, const float* __restrict__ w_ih,
    const float* __restrict__ b_ih, const float* __restrict__ b_hh)
{
    __shared__ float4 sx[256 * 8];     // 32 KB: 256 rows of x
    __shared__ float  swp[32 * 33];    // padded weights (conflict-free row read)

    const int tid  = threadIdx.x;
    const int lane = tid & 31;
    const int wid  = tid >> 5;

    // stage weights coalesced, pre-scaled
#pragma unroll
    for (int k = 0; k < 4; k++) {
        const int idx = tid + k * 256;          // 1024 floats
        const int g = idx >> 5, j = idx & 31;
        const float s = ((g >> 3) == 2) ? 1.f : 0.5f;
        swp[g * 33 + j] = w_ih[idx] * s;
    }

    // stage x coalesced: 256 rows
    const size_t rowbase = (size_t)blockIdx.x * 256;
    const float4* xg4 = (const float4*)x + rowbase * 8;
#pragma unroll
    for (int i = 0; i < 8; i++) sx[tid + i * 256] = xg4[tid + i * 256];

    __syncthreads();

    // per-lane gate weights + bias
    float w[32];
#pragma unroll
    for (int j = 0; j < 32; j++) w[j] = swp[lane * 33 + j];
    const float s2 = ((lane >> 3) == 2) ? 1.f : 0.5f;
    const float bias = (b_ih[lane] + b_hh[lane]) * s2;

    // warp computes rows [wid*32, wid*32+32)
    float* op = g_xg + (rowbase + wid * 32) * 32 + lane;
    const float4* xr0 = &sx[wid * 32 * 8];

#pragma unroll 4
    for (int r = 0; r < 32; r++) {
        const float4* xr = xr0 + r * 8;
        float a0 = bias, a1 = 0.f, a2 = 0.f, a3 = 0.f;
#pragma unroll
        for (int j4 = 0; j4 < 8; j4++) {
            const float4 v = xr[j4];            // broadcast LDS.128
            a0 = fmaf(w[j4 * 4 + 0], v.x, a0);
            a1 = fmaf(w[j4 * 4 + 1], v.y, a1);
            a2 = fmaf(w[j4 * 4 + 2], v.z, a2);
            a3 = fmaf(w[j4 * 4 + 3], v.w, a3);
        }
        op[(size_t)r * 32] = (a0 + a1) + (a2 + a3);   // coalesced STG.32
    }
}

// ---------------------------------------------------------------------------
// K2: sequential LSTM, one warp per batch element, lane = gate.
//     Branch-free inner loop: all lanes store every step (lanes>=8 to dump),
//     prefetch conditional removed by peeling the last PF steps.
// ---------------------------------------------------------------------------
#define PF 4
__global__ void __launch_bounds__(32, 1) k2_lstm(
    const float* __restrict__ h0, const float* __restrict__ c0,
    const float* __restrict__ w_hh, float* __restrict__ out)
{
    const int lane = threadIdx.x;
    const int b    = blockIdx.x;
    const int unit = lane & 7;
    const float scale = ((lane >> 3) == 2) ? 1.f : 0.5f;

    float whh[8];
#pragma unroll
    for (int j = 0; j < 8; j++) whh[j] = w_hh[lane * 8 + j] * scale;

    float h = h0[b * 8 + unit];
    float c = c0[b * 8 + unit];

    const float* xp = g_xg + b * 32 + lane;     // step stride: BATCH*32

    // branch-free store target: lanes 0-7 -> g_ys (stride BATCH*8/step),
    // lanes 8-31 -> dump (stride 0)
    float* ybase = (lane < 8) ? (g_ys + b * 8 + unit) : (g_dump + b * 32 + lane);
    const size_t ystride = (lane < 8) ? (size_t)(BATCH * 8) : 0;

    float buf[PF];
#pragma unroll
    for (int k = 0; k < PF; k++) buf[k] = __ldg(xp + (size_t)k * (BATCH * 32));

#define K2_STEP(T2, DO_PF)                                                   \
    {                                                                        \
        const int k_ = (T2) & (PF - 1);                                      \
        float a0 = buf[k_], a1 = 0.f, a2 = 0.f, a3 = 0.f;                    \
        a0 = fmaf(whh[0], __shfl_sync(0xffffffffu, h, 0), a0);               \
        a1 = fmaf(whh[1], __shfl_sync(0xffffffffu, h, 1), a1);               \
        a2 = fmaf(whh[2], __shfl_sync(0xffffffffu, h, 2), a2);               \
        a3 = fmaf(whh[3], __shfl_sync(0xffffffffu, h, 3), a3);               \
        a0 = fmaf(whh[4], __shfl_sync(0xffffffffu, h, 4), a0);               \
        a1 = fmaf(whh[5], __shfl_sync(0xffffffffu, h, 5), a1);               \
        a2 = fmaf(whh[6], __shfl_sync(0xffffffffu, h, 6), a2);               \
        a3 = fmaf(whh[7], __shfl_sync(0xffffffffu, h, 7), a3);               \
        const float acc = (a0 + a1) + (a2 + a3);                             \
        const float v = tanha(acc);                                          \
        const float iv = __shfl_sync(0xffffffffu, v, unit);                  \
        const float fv = __shfl_sync(0xffffffffu, v, unit + 8);              \
        const float gv = __shfl_sync(0xffffffffu, v, unit + 16);             \
        const float ov = __shfl_sync(0xffffffffu, v, unit + 24);             \
        const float fg = fmaf(fv, 0.5f, 0.5f);                               \
        const float ig = fmaf(iv, 0.5f, 0.5f);                               \
        const float og = fmaf(ov, 0.5f, 0.5f);                               \
        c = fmaf(fg, c, ig * gv);                                            \
        h = og * tanha(c);                                                   \
        ybase[(size_t)(T2) * ystride] = h;                                   \
        if (DO_PF)                                                           \
            buf[k_] = __ldg(xp + (size_t)((T2) + PF) * (BATCH * 32));        \
    }

    int t = 0;
#pragma unroll 1
    for (; t < S_LEN - PF; t += PF) {
#pragma unroll
        for (int k = 0; k < PF; k++) K2_STEP(t + k, true)
    }
#pragma unroll
    for (int k = 0; k < PF; k++) K2_STEP(t + k, false)

    if (lane < 8) {
        out[(size_t)NROWS * OUTSZ + b * 8 + lane] = h;                 // h_f
        out[(size_t)NROWS * OUTSZ + BATCH * HID + b * 8 + lane] = c;   // c_f
    }
}

// ---------------------------------------------------------------------------
// K3: residual MLP head. Lane per (t,b) row through 80-block chain,
//     warp-transpose via shfl for the 128-wide expansion -> STG.128.
// ---------------------------------------------------------------------------
__global__ void __launch_bounds__(256) k3_res(
    const float* __restrict__ w_in,  const float* __restrict__ b_in,
    const float* __restrict__ rb_w1, const float* __restrict__ rb_b1,
    const float* __restrict__ rb_w2, const float* __restrict__ rb_b2,
    const float* __restrict__ w_bn,  const float* __restrict__ b_bn,
    const float* __restrict__ w_out, const float* __restrict__ b_out,
    float* __restrict__ out)
{
    __shared__ float4 s_w1[NBLK], s_w2[NBLK], s_b2[NBLK];
    __shared__ float  s_b1[NBLK];
    for (int i = threadIdx.x; i < NBLK; i += blockDim.x) {
        s_w1[i] = ((const float4*)rb_w1)[i];
        s_w2[i] = ((const float4*)rb_w2)[i];
        s_b2[i] = ((const float4*)rb_b2)[i];
        s_b1[i] = rb_b1[i];
    }
    __syncthreads();

    const int lane  = threadIdx.x & 31;
    const int warpg = (blockIdx.x * blockDim.x + threadIdx.x) >> 5;
    const int base  = warpg * 32;           // 16384 warps cover 524288 rows
    const int e     = base + lane;

    const float4 ha = *(const float4*)(g_ys + (size_t)e * 8);
    const float4 hb = *(const float4*)(g_ys + (size_t)e * 8 + 4);
    const float hv[8] = {ha.x, ha.y, ha.z, ha.w, hb.x, hb.y, hb.z, hb.w};

    float y[4];
#pragma unroll
    for (int i = 0; i < 4; i++) {
        float a = b_in[i];
#pragma unroll
        for (int j = 0; j < 8; j++) a = fmaf(w_in[i * 8 + j], hv[j], a);
        y[i] = leaky(a);
    }

#pragma unroll 2
    for (int blk = 0; blk < NBLK; blk++) {
        const float4 w1 = s_w1[blk];
        const float4 w2 = s_w2[blk];
        const float4 b2 = s_b2[blk];
        float z = s_b1[blk];
        z = fmaf(w1.x, y[0], z);
        z = fmaf(w1.y, y[1], z);
        z = fmaf(w1.z, y[2], z);
        z = fmaf(w1.w, y[3], z);
        z = leaky(z);
        y[0] = leaky(fmaf(w2.x, z, y[0]) + b2.x);
        y[1] = leaky(fmaf(w2.y, z, y[1]) + b2.y);
        y[2] = leaky(fmaf(w2.z, z, y[2]) + b2.z);
        y[3] = leaky(fmaf(w2.w, z, y[3]) + b2.w);
    }

    float yb = b_bn[0];
    yb = fmaf(w_bn[0], y[0], yb);
    yb = fmaf(w_bn[1], y[1], yb);
    yb = fmaf(w_bn[2], y[2], yb);
    yb = fmaf(w_bn[3], y[3], yb);
    yb = leaky(yb);

    // sigmoid(a*w+b) = 0.5 + 0.5*tanh(0.5*(a*w+b)) -> pre-halved w,b
    float4 wo = *(const float4*)(w_out + lane * 4);
    float4 bo = *(const float4*)(b_out + lane * 4);
    wo.x *= 0.5f; wo.y *= 0.5f; wo.z *= 0.5f; wo.w *= 0.5f;
    bo.x *= 0.5f; bo.y *= 0.5f; bo.z *= 0.5f; bo.w *= 0.5f;
    float* op = out + (size_t)base * OUTSZ + lane * 4;

#pragma unroll
    for (int cidx = 0; cidx < 32; cidx++) {
        const float ybc = __shfl_sync(0xffffffffu, yb, cidx);
        float4 o;
        o.x = fmaf(tanha(fmaf(ybc, wo.x, bo.x)), 0.5f, 0.5f);
        o.y = fmaf(tanha(fmaf(ybc, wo.y, bo.y)), 0.5f, 0.5f);
        o.z = fmaf(tanha(fmaf(ybc, wo.z, bo.z)), 0.5f, 0.5f);
        o.w = fmaf(tanha(fmaf(ybc, wo.w, bo.w)), 0.5f, 0.5f);
        *(float4*)(op + (size_t)cidx * OUTSZ) = o;
    }
}

// ---------------------------------------------------------------------------
extern "C" void kernel_launch(void* const* d_in, const int* in_sizes, int n_in,
                              void* d_out, int out_size)
{
    const float* x     = (const float*)d_in[0];
    const float* h     = (const float*)d_in[1];
    const float* c     = (const float*)d_in[2];
    const float* w_ih  = (const float*)d_in[3];
    const float* w_hh  = (const float*)d_in[4];
    const float* b_ih  = (const float*)d_in[5];
    const float* b_hh  = (const float*)d_in[6];
    const float* w_in  = (const float*)d_in[7];
    const float* b_in  = (const float*)d_in[8];
    const float* rb_w1 = (const float*)d_in[9];
    const float* rb_b1 = (const float*)d_in[10];
    const float* rb_w2 = (const float*)d_in[11];
    const float* rb_b2 = (const float*)d_in[12];
    const float* w_bn  = (const float*)d_in[13];
    const float* b_bn  = (const float*)d_in[14];
    const float* w_out = (const float*)d_in[15];
    const float* b_out = (const float*)d_in[16];
    float* out = (float*)d_out;

    k1_xw<<<2048, 256>>>(x, w_ih, b_ih, b_hh);
    k2_lstm<<<BATCH, 32>>>(h, c, w_hh, out);
    k3_res<<<2048, 256>>>(w_in, b_in, rb_w1, rb_b1, rb_w2, rb_b2,
                          w_bn, b_bn, w_out, b_out, out);
}

// round 4
// speedup vs baseline: 1.2426x; 1.2426x over previous
#include <cuda_runtime.h>
#include <cstdint>

#define S_LEN 2048
#define BATCH 256
#define INSZ  32
#define HID   8
#define G4    32          // 4*HID gates
#define NBLK  80
#define OUTSZ 128
#define NROWS (S_LEN*BATCH)   // 524288

// Scratch (__device__ globals; no runtime allocation)
// g_xg layout: [row][unit*4 + gate_type]  (i,f,g,o interleaved per unit)
__device__ float g_xg[(size_t)NROWS * G4];   // 64 MB
__device__ float g_ys[(size_t)NROWS * HID];  // 16 MB: LSTM hidden outputs

__device__ __forceinline__ float tanha(float x) {
    float r; asm("tanh.approx.f32 %0, %1;" : "=f"(r) : "f"(x)); return r;
}
__device__ __forceinline__ float leaky(float v) { return fmaxf(v, 0.01f * v); }

// ---------------------------------------------------------------------------
// K1: xg[row][u*4+t] = s(t) * ( x[row].w_ih[t*8+u] + b_ih + b_hh )
//     s = 0.5 for sigmoid gates (i,f,o: t=0,1,3), 1.0 for tanh gate (t=2).
//     Coalesced smem staging of x; lane = gate, rows sequential; the store
//     column is the unit-major permutation (still one 128B line per warp).
// ---------------------------------------------------------------------------
__global__ void __launch_bounds__(256) k1_xw(
    const float* __restrict__ x, const float* __restrict__ w_ih,
    const float* __restrict__ b_ih, const float* __restrict__ b_hh)
{
    __shared__ float4 sx[256 * 8];     // 32 KB: 256 rows of x
    __shared__ float  swp[32 * 33];    // padded weights (conflict-free row read)

    const int tid  = threadIdx.x;
    const int lane = tid & 31;
    const int wid  = tid >> 5;

    // stage weights coalesced, pre-scaled
#pragma unroll
    for (int k = 0; k < 4; k++) {
        const int idx = tid + k * 256;          // 1024 floats
        const int g = idx >> 5, j = idx & 31;
        const float s = ((g >> 3) == 2) ? 1.f : 0.5f;
        swp[g * 33 + j] = w_ih[idx] * s;
    }

    // stage x coalesced: 256 rows
    const size_t rowbase = (size_t)blockIdx.x * 256;
    const float4* xg4 = (const float4*)x + rowbase * 8;
#pragma unroll
    for (int i = 0; i < 8; i++) sx[tid + i * 256] = xg4[tid + i * 256];

    __syncthreads();

    // per-lane gate weights + bias (lane = gate index g = type*8+unit)
    float w[32];
#pragma unroll
    for (int j = 0; j < 32; j++) w[j] = swp[lane * 33 + j];
    const float s2 = ((lane >> 3) == 2) ? 1.f : 0.5f;
    const float bias = (b_ih[lane] + b_hh[lane]) * s2;

    // unit-major output column: u*4 + type
    const int ocol = (lane & 7) * 4 + (lane >> 3);

    float* op = g_xg + (rowbase + wid * 32) * 32 + ocol;
    const float4* xr0 = &sx[wid * 32 * 8];

#pragma unroll 4
    for (int r = 0; r < 32; r++) {
        const float4* xr = xr0 + r * 8;
        float a0 = bias, a1 = 0.f, a2 = 0.f, a3 = 0.f;
#pragma unroll
        for (int j4 = 0; j4 < 8; j4++) {
            const float4 v = xr[j4];            // broadcast LDS.128
            a0 = fmaf(w[j4 * 4 + 0], v.x, a0);
            a1 = fmaf(w[j4 * 4 + 1], v.y, a1);
            a2 = fmaf(w[j4 * 4 + 2], v.z, a2);
            a3 = fmaf(w[j4 * 4 + 3], v.w, a3);
        }
        op[(size_t)r * 32] = (a0 + a1) + (a2 + a3);   // coalesced STG.32
    }
}

// ---------------------------------------------------------------------------
// K2: sequential LSTM. 4 batch elements per warp; lane = (bsub, unit).
//     Each lane computes ALL FOUR gates for its unit -> no gather shuffle.
//     h exchanged via width-8 shfl (one broadcast round per step).
//     Per-step xg = one LDG.128 (i,f,g,o of this unit), prefetched PF deep.
//     Stores fully coalesced, all 32 lanes, no predication.
// ---------------------------------------------------------------------------
#define PF 8
__global__ void __launch_bounds__(32, 1) k2_lstm(
    const float* __restrict__ h0, const float* __restrict__ c0,
    const float* __restrict__ w_hh, float* __restrict__ out)
{
    const int lane = threadIdx.x;
    const int blk  = blockIdx.x;           // 64 blocks, 4 batch elems each
    const int unit = lane & 7;
    const int bsub = lane >> 3;
    const int b    = blk * 4 + bsub;

    // weights: gate rows unit, unit+8, unit+16, unit+24; pre-scale 0.5 (i,f,o)
    float w[4][8];
#pragma unroll
    for (int t = 0; t < 4; t++) {
        const float s = (t == 2) ? 1.f : 0.5f;
#pragma unroll
        for (int j = 0; j < 8; j++) w[t][j] = w_hh[(t * 8 + unit) * 8 + j] * s;
    }

    float h = h0[blk * 32 + lane];   // [b][u] = blk*32 + bsub*8 + unit = blk*32+lane
    float c = c0[blk * 32 + lane];

    // xg float4 pointer: row = t*BATCH + b; float4 index = row*8 + unit
    const float4* xp = (const float4*)g_xg + (size_t)b * 8 + unit;  // + t*2048
    float* yp = g_ys + blk * 32 + lane;                              // + t*2048

    float4 buf[PF];
#pragma unroll
    for (int k = 0; k < PF; k++) buf[k] = __ldg(xp + (size_t)k * 2048);

#define K2V2_STEP(T2, DO_PF)                                                  \
    {                                                                         \
        const int k_ = (T2) & (PF - 1);                                       \
        float hs[8];                                                          \
        _Pragma("unroll")                                                     \
        for (int j = 0; j < 8; j++) hs[j] = __shfl_sync(0xffffffffu, h, j, 8);\
        const float4 xg = buf[k_];                                            \
        float i0 = xg.x, i1 = 0.f, f0 = xg.y, f1 = 0.f;                       \
        float gg0 = xg.z, gg1 = 0.f, o0 = xg.w, o1 = 0.f;                     \
        _Pragma("unroll")                                                     \
        for (int j = 0; j < 4; j++) {                                         \
            i0  = fmaf(w[0][j], hs[j], i0);                                   \
            i1  = fmaf(w[0][j + 4], hs[j + 4], i1);                           \
            f0  = fmaf(w[1][j], hs[j], f0);                                   \
            f1  = fmaf(w[1][j + 4], hs[j + 4], f1);                           \
            gg0 = fmaf(w[2][j], hs[j], gg0);                                  \
            gg1 = fmaf(w[2][j + 4], hs[j + 4], gg1);                          \
            o0  = fmaf(w[3][j], hs[j], o0);                                   \
            o1  = fmaf(w[3][j + 4], hs[j + 4], o1);                           \
        }                                                                     \
        const float vi = tanha(i0 + i1);                                      \
        const float vf = tanha(f0 + f1);                                      \
        const float vg = tanha(gg0 + gg1);                                    \
        const float vo = tanha(o0 + o1);                                      \
        const float ig = fmaf(vi, 0.5f, 0.5f);                                \
        const float fg = fmaf(vf, 0.5f, 0.5f);                                \
        const float og = fmaf(vo, 0.5f, 0.5f);                                \
        c = fmaf(fg, c, ig * vg);                                             \
        h = og * tanha(c);                                                    \
        yp[(size_t)(T2) * 2048] = h;                                          \
        if (DO_PF)                                                            \
            buf[k_] = __ldg(xp + (size_t)((T2) + PF) * 2048);                 \
    }

    int t = 0;
#pragma unroll 1
    for (; t < S_LEN - PF; t += PF) {
#pragma unroll
        for (int k = 0; k < PF; k++) K2V2_STEP(t + k, true)
    }
#pragma unroll
    for (int k = 0; k < PF; k++) K2V2_STEP(t + k, false)

    out[(size_t)NROWS * OUTSZ + blk * 32 + lane] = h;                 // h_f
    out[(size_t)NROWS * OUTSZ + BATCH * HID + blk * 32 + lane] = c;   // c_f
}

// ---------------------------------------------------------------------------
// K3: residual MLP head. Lane per (t,b) row through 80-block chain,
//     warp-transpose via shfl for the 128-wide expansion -> STG.128.
// ---------------------------------------------------------------------------
__global__ void __launch_bounds__(256) k3_res(
    const float* __restrict__ w_in,  const float* __restrict__ b_in,
    const float* __restrict__ rb_w1, const float* __restrict__ rb_b1,
    const float* __restrict__ rb_w2, const float* __restrict__ rb_b2,
    const float* __restrict__ w_bn,  const float* __restrict__ b_bn,
    const float* __restrict__ w_out, const float* __restrict__ b_out,
    float* __restrict__ out)
{
    __shared__ float4 s_w1[NBLK], s_w2[NBLK], s_b2[NBLK];
    __shared__ float  s_b1[NBLK];
    for (int i = threadIdx.x; i < NBLK; i += blockDim.x) {
        s_w1[i] = ((const float4*)rb_w1)[i];
        s_w2[i] = ((const float4*)rb_w2)[i];
        s_b2[i] = ((const float4*)rb_b2)[i];
        s_b1[i] = rb_b1[i];
    }
    __syncthreads();

    const int lane  = threadIdx.x & 31;
    const int warpg = (blockIdx.x * blockDim.x + threadIdx.x) >> 5;
    const int base  = warpg * 32;           // 16384 warps cover 524288 rows
    const int e     = base + lane;

    const float4 ha = *(const float4*)(g_ys + (size_t)e * 8);
    const float4 hb = *(const float4*)(g_ys + (size_t)e * 8 + 4);
    const float hv[8] = {ha.x, ha.y, ha.z, ha.w, hb.x, hb.y, hb.z, hb.w};

    float y[4];
#pragma unroll
    for (int i = 0; i < 4; i++) {
        float a = b_in[i];
#pragma unroll
        for (int j = 0; j < 8; j++) a = fmaf(w_in[i * 8 + j], hv[j], a);
        y[i] = leaky(a);
    }

#pragma unroll 2
    for (int blk = 0; blk < NBLK; blk++) {
        const float4 w1 = s_w1[blk];
        const float4 w2 = s_w2[blk];
        const float4 b2 = s_b2[blk];
        float z = s_b1[blk];
        z = fmaf(w1.x, y[0], z);
        z = fmaf(w1.y, y[1], z);
        z = fmaf(w1.z, y[2], z);
        z = fmaf(w1.w, y[3], z);
        z = leaky(z);
        y[0] = leaky(fmaf(w2.x, z, y[0]) + b2.x);
        y[1] = leaky(fmaf(w2.y, z, y[1]) + b2.y);
        y[2] = leaky(fmaf(w2.z, z, y[2]) + b2.z);
        y[3] = leaky(fmaf(w2.w, z, y[3]) + b2.w);
    }

    float yb = b_bn[0];
    yb = fmaf(w_bn[0], y[0], yb);
    yb = fmaf(w_bn[1], y[1], yb);
    yb = fmaf(w_bn[2], y[2], yb);
    yb = fmaf(w_bn[3], y[3], yb);
    yb = leaky(yb);

    // sigmoid(a*w+b) = 0.5 + 0.5*tanh(0.5*(a*w+b)) -> pre-halved w,b
    float4 wo = *(const float4*)(w_out + lane * 4);
    float4 bo = *(const float4*)(b_out + lane * 4);
    wo.x *= 0.5f; wo.y *= 0.5f; wo.z *= 0.5f; wo.w *= 0.5f;
    bo.x *= 0.5f; bo.y *= 0.5f; bo.z *= 0.5f; bo.w *= 0.5f;
    float* op = out + (size_t)base * OUTSZ + lane * 4;

#pragma unroll
    for (int cidx = 0; cidx < 32; cidx++) {
        const float ybc = __shfl_sync(0xffffffffu, yb, cidx);
        float4 o;
        o.x = fmaf(tanha(fmaf(ybc, wo.x, bo.x)), 0.5f, 0.5f);
        o.y = fmaf(tanha(fmaf(ybc, wo.y, bo.y)), 0.5f, 0.5f);
        o.z = fmaf(tanha(fmaf(ybc, wo.z, bo.z)), 0.5f, 0.5f);
        o.w = fmaf(tanha(fmaf(ybc, wo.w, bo.w)), 0.5f, 0.5f);
        *(float4*)(op + (size_t)cidx * OUTSZ) = o;
    }
}

// ---------------------------------------------------------------------------
extern "C" void kernel_launch(void* const* d_in, const int* in_sizes, int n_in,
                              void* d_out, int out_size)
{
    const float* x     = (const float*)d_in[0];
    const float* h     = (const float*)d_in[1];
    const float* c     = (const float*)d_in[2];
    const float* w_ih  = (const float*)d_in[3];
    const float* w_hh  = (const float*)d_in[4];
    const float* b_ih  = (const float*)d_in[5];
    const float* b_hh  = (const float*)d_in[6];
    const float* w_in  = (const float*)d_in[7];
    const float* b_in  = (const float*)d_in[8];
    const float* rb_w1 = (const float*)d_in[9];
    const float* rb_b1 = (const float*)d_in[10];
    const float* rb_w2 = (const float*)d_in[11];
    const float* rb_b2 = (const float*)d_in[12];
    const float* w_bn  = (const float*)d_in[13];
    const float* b_bn  = (const float*)d_in[14];
    const float* w_out = (const float*)d_in[15];
    const float* b_out = (const float*)d_in[16];
    float* out = (float*)d_out;

    k1_xw<<<2048, 256>>>(x, w_ih, b_ih, b_hh);
    k2_lstm<<<BATCH / 4, 32>>>(h, c, w_hh, out);
    k3_res<<<2048, 256>>>(w_in, b_in, rb_w1, rb_b1, rb_w2, rb_b2,
                          w_bn, b_bn, w_out, b_out, out);
}